// round 10
// baseline (speedup 1.0000x reference)
#include <cuda_runtime.h>
#include <cuda_fp16.h>
#include <cstdint>

static constexpr int T_TOK = 8192;
static constexpr int H_DIM = 2048;
static constexpr int E_NUM = 8;
static constexpr int I_DIM = 1024;
static constexpr int NPAIR = T_TOK * 2;

// ---------------- scratch (static device globals; no allocations) ----------------
__device__ __align__(128) __half g_xh[(size_t)T_TOK * H_DIM];   // x in fp16 (router writes)
__device__ __align__(128) __half g_yh[(size_t)NPAIR * I_DIM];   // silu(g)*u, fp16
__device__ __align__(128) __half g_zh[(size_t)NPAIR * H_DIM];   // down-proj out, fp16
__device__ int   g_topidx[NPAIR];
__device__ float g_topw[NPAIR];
__device__ int   g_pairloc[NPAIR];
__device__ int   g_bucket[NPAIR];
__device__ int   g_counts[E_NUM];
__device__ int   g_offsets[E_NUM + 1];
__device__ int   g_cursors[E_NUM];

// ---------------- PTX helpers ----------------
#define SWZ128(o) ((o) ^ (((o) >> 3) & 0x70))

__device__ __forceinline__ uint32_t h2u(__half2 h) {
    return *reinterpret_cast<uint32_t*>(&h);
}
__device__ __forceinline__ void cp16(uint32_t dst, const void* src) {
    asm volatile("cp.async.cg.shared.global [%0], [%1], 16;" :: "r"(dst), "l"(src) : "memory");
}
__device__ __forceinline__ void cp_commit() {
    asm volatile("cp.async.commit_group;" ::: "memory");
}
template <int N>
__device__ __forceinline__ void cp_wait() {
    asm volatile("cp.async.wait_group %0;" :: "n"(N) : "memory");
}
__device__ __forceinline__ void ldsm4(uint32_t* d, uint32_t addr) {
    asm volatile("ldmatrix.sync.aligned.m8n8.x4.shared.b16 {%0,%1,%2,%3}, [%4];"
                 : "=r"(d[0]), "=r"(d[1]), "=r"(d[2]), "=r"(d[3]) : "r"(addr));
}
__device__ __forceinline__ void mma16816(float* c, const uint32_t* a, uint32_t b0, uint32_t b1) {
    asm volatile(
        "mma.sync.aligned.m16n8k16.row.col.f32.f16.f16.f32 "
        "{%0,%1,%2,%3}, {%4,%5,%6,%7}, {%8,%9}, {%0,%1,%2,%3};"
        : "+f"(c[0]), "+f"(c[1]), "+f"(c[2]), "+f"(c[3])
        : "r"(a[0]), "r"(a[1]), "r"(a[2]), "r"(a[3]), "r"(b0), "r"(b1));
}

// ---------------- tiny setup kernels ----------------
__global__ void init_kernel() {
    int i = threadIdx.x;
    if (i < E_NUM) { g_counts[i] = 0; g_cursors[i] = 0; }
}

// One warp per token: router logits + top-2, AND writes the fp16 copy of x.
__global__ void router_kernel(const float* __restrict__ x,
                              const float* __restrict__ wg) {
    int warp = threadIdx.x >> 5, lane = threadIdx.x & 31;
    int t = blockIdx.x * 8 + warp;
    if (t >= T_TOK) return;
    float acc[E_NUM];
#pragma unroll
    for (int e = 0; e < E_NUM; e++) acc[e] = 0.f;
    const float4* xr = (const float4*)(x + (size_t)t * H_DIM);
    __half2* xh = (__half2*)(g_xh + (size_t)t * H_DIM);
    for (int h4 = lane; h4 < H_DIM / 4; h4 += 32) {
        float4 xv = xr[h4];
        xh[h4 * 2 + 0] = __floats2half2_rn(xv.x, xv.y);
        xh[h4 * 2 + 1] = __floats2half2_rn(xv.z, xv.w);
#pragma unroll
        for (int e = 0; e < E_NUM; e++) {
            float4 wv = ((const float4*)(wg + (size_t)e * H_DIM))[h4];
            acc[e] += xv.x * wv.x + xv.y * wv.y + xv.z * wv.z + xv.w * wv.w;
        }
    }
#pragma unroll
    for (int e = 0; e < E_NUM; e++)
#pragma unroll
        for (int off = 16; off; off >>= 1)
            acc[e] += __shfl_xor_sync(0xffffffffu, acc[e], off);
    if (lane == 0) {
        int i0 = 0;
        for (int e = 1; e < E_NUM; e++) if (acc[e] > acc[i0]) i0 = e;
        int i1 = (i0 == 0) ? 1 : 0;
        for (int e = 0; e < E_NUM; e++) if (e != i0 && acc[e] > acc[i1]) i1 = e;
        float w0 = 1.f / (1.f + expf(acc[i1] - acc[i0]));
        g_topidx[2 * t] = i0; g_topidx[2 * t + 1] = i1;
        g_topw[2 * t] = w0;   g_topw[2 * t + 1] = 1.f - w0;
        atomicAdd(&g_counts[i0], 1);
        atomicAdd(&g_counts[i1], 1);
    }
}

__global__ void scan_kernel() {
    if (threadIdx.x == 0) {
        int s = 0;
        for (int e = 0; e < E_NUM; e++) { g_offsets[e] = s; s += g_counts[e]; }
        g_offsets[E_NUM] = s;
    }
}

__global__ void scatter_kernel() {
    int t = blockIdx.x * blockDim.x + threadIdx.x;
    if (t >= T_TOK) return;
#pragma unroll
    for (int k = 0; k < 2; k++) {
        int e = g_topidx[2 * t + k];
        int pos = atomicAdd(&g_cursors[e], 1);
        int glob = g_offsets[e] + pos;
        g_bucket[glob] = t;
        g_pairloc[2 * t + k] = glob;
    }
}

// ---------------- fp16 mma grouped GEMM, BK=128, 3-stage pipeline ----------------
// Stage layout: A sub-tile0 (16KB, k 0-63) | A sub-tile1 (16KB, k 64-127)
//             | B sub-tile0 (16KB)         | B sub-tile1 (16KB)   = 64KB/stage.
// Each sub-tile is 128 rows x 128 bytes with SW128 xor swizzle.
// A (fp16, cp.async): MODE 0 = gather(g_xh); MODE 1 = g_yh contiguous.
// B (fp32 -> fp16 in-register, STS, two half-batches): MODE 0 rows 0-63 = w1,
//   rows 64-127 = w3; MODE 1 = w2 rows.
static constexpr int BM = 128, BN = 128, BK = 128;     // BK in halves
static constexpr int NSTG = 3;
static constexpr int SUB_B = 128 * 128;                // 16384 bytes per sub-tile
static constexpr int MAT_B = 2 * SUB_B;                // 32768 per matrix per stage
static constexpr int STG_B = 2 * MAT_B;                // 65536 per stage
static constexpr int SMEM_BYTES = NSTG * STG_B;        // 196608

template <int MODE>
__global__ __launch_bounds__(256, 1)
void moe_gemm_kernel(const float* __restrict__ W0,    // w1 / w2 (fp32)
                     const float* __restrict__ W1)    // w3 / unused
{
    constexpr int KD = (MODE == 0) ? H_DIM : I_DIM;
    constexpr int NK = KD / BK;                         // 16 / 8

    const int e    = blockIdx.z;
    const int row0 = g_offsets[e];
    const int cnt  = g_offsets[e + 1] - row0;
    const int m0   = blockIdx.y * BM;
    if (m0 >= cnt) return;

    extern __shared__ char smem[];
    const uint32_t smb = (uint32_t)__cvta_generic_to_shared(smem);

    const int tid = threadIdx.x;
    const int wid = tid >> 5, lane = tid & 31;
    const int wm = wid & 1, wn = wid >> 1;              // 2(M) x 4(N) warps
    const int mbase = wm * 64, nbase = wn * 32;

    const int n0I = blockIdx.x * 64;                    // MODE 0
    const int n0  = blockIdx.x * BN;                    // MODE 1

    // ---- A: 8 cp.async chunks of 16B per thread per stage ----
    const __half* gpA[8];
    uint32_t soA[8];
#pragma unroll
    for (int q = 0; q < 8; q++) {
        int i = tid + q * 256;                           // 0..2047
        int sub = i >> 10;                               // k-half
        int w = i & 1023;
        int r = w >> 3, c = w & 7;
        int lr = m0 + r; if (lr >= cnt) lr = cnt - 1;
        size_t arow = (MODE == 0) ? (size_t)g_bucket[row0 + lr] * KD
                                  : (size_t)(row0 + lr) * KD;
        gpA[q] = ((MODE == 0) ? g_xh : g_yh) + arow + sub * 64 + c * 8;
        soA[q] = (uint32_t)(sub * SUB_B) + (uint32_t)SWZ128(r * 128 + c * 16);
    }
    // ---- B: 8 fp32 chunks (32B each) per thread per stage, converted to fp16 ----
    const float4* gpB[8];
    uint32_t soB[8];
#pragma unroll
    for (int q = 0; q < 8; q++) {
        int j = tid + q * 256;                           // 0..2047
        int sub = j >> 10;
        int w = j & 1023;
        int r = w >> 3, c = w & 7;
        const float* bb;
        if (MODE == 0)
            bb = (r < 64) ? (W0 + ((size_t)e * I_DIM + (n0I + r)) * KD)
                          : (W1 + ((size_t)e * I_DIM + (n0I + r - 64)) * KD);
        else
            bb = W0 + ((size_t)e * H_DIM + (n0 + r)) * KD;
        gpB[q] = (const float4*)(bb + sub * 64 + c * 8);
        soB[q] = (uint32_t)MAT_B + (uint32_t)(sub * SUB_B) + (uint32_t)SWZ128(r * 128 + c * 16);
    }

    // ---- ldmatrix address bases (within a 128B-row sub-tile) ----
    const int lrow = lane & 15;
    const uint32_t kc16 = (uint32_t)(lane >> 4) * 16;
    uint32_t aRaw[4], aM[4], bRaw[2], bM[2];
#pragma unroll
    for (int i = 0; i < 4; i++) {
        int r = mbase + i * 16 + lrow;
        aRaw[i] = (uint32_t)r * 128 + kc16;
        aM[i] = (uint32_t)(r & 7) << 4;
    }
#pragma unroll
    for (int j = 0; j < 2; j++) {
        int r = nbase + j * 16 + lrow;
        bRaw[j] = (uint32_t)r * 128 + kc16;
        bM[j] = (uint32_t)(r & 7) << 4;
    }

    float acc[4][4][4];
#pragma unroll
    for (int i = 0; i < 4; i++)
#pragma unroll
        for (int j = 0; j < 4; j++)
#pragma unroll
            for (int q = 0; q < 4; q++) acc[i][j][q] = 0.f;

    // ---- prologue: stages 0..NSTG-2 (A async; B blocking LDG+cvt+STS) ----
#pragma unroll
    for (int s = 0; s < NSTG - 1; s++) {
        uint32_t base = smb + (uint32_t)s * STG_B;
#pragma unroll
        for (int q = 0; q < 8; q++) { cp16(base + soA[q], gpA[q]); gpA[q] += BK; }
#pragma unroll
        for (int q = 0; q < 8; q++) {
            float4 v0 = gpB[q][0], v1 = gpB[q][1];
            gpB[q] += BK / 4;
            uint4 h;
            h.x = h2u(__floats2half2_rn(v0.x, v0.y));
            h.y = h2u(__floats2half2_rn(v0.z, v0.w));
            h.z = h2u(__floats2half2_rn(v1.x, v1.y));
            h.w = h2u(__floats2half2_rn(v1.z, v1.w));
            *(uint4*)(smem + (size_t)s * STG_B + soB[q]) = h;
        }
        cp_commit();
    }

    // ---- mainloop ----
    for (int it = 0; it < NK; it++) {
        cp_wait<NSTG - 2>();
        __syncthreads();

        const bool act = (it + NSTG - 1 < NK);
        const uint32_t slot = (uint32_t)((it + NSTG - 1) % NSTG);
        const uint32_t nbB = slot * STG_B;

        if (act) {
            uint32_t base = smb + slot * STG_B;
#pragma unroll
            for (int q = 0; q < 8; q++) { cp16(base + soA[q], gpA[q]); gpA[q] += BK; }
        }
        // B half 0: LDG now, STS after first MMA half (latency hidden by MMAs)
        float4 br0[4], br1[4];
        if (act) {
#pragma unroll
            for (int q = 0; q < 4; q++) {
                br0[q] = gpB[q][0]; br1[q] = gpB[q][1]; gpB[q] += BK / 4;
            }
        }

        const uint32_t sA = smb + (uint32_t)(it % NSTG) * STG_B;
        const uint32_t sB = sA + MAT_B;

        // ---- kk 0..3 (sub-tile 0) ----
#pragma unroll
        for (int kk = 0; kk < 4; kk++) {
            uint32_t a[4][4], b[2][4];
#pragma unroll
            for (int i = 0; i < 4; i++)
                ldsm4(a[i], sA + ((aRaw[i] + kk * 32) ^ aM[i]));
#pragma unroll
            for (int j = 0; j < 2; j++)
                ldsm4(b[j], sB + ((bRaw[j] + kk * 32) ^ bM[j]));
#pragma unroll
            for (int i = 0; i < 4; i++)
#pragma unroll
                for (int jn = 0; jn < 4; jn++)
                    mma16816(acc[i][jn], a[i],
                             b[jn >> 1][jn & 1], b[jn >> 1][(jn & 1) + 2]);
        }

        // STS half 0; LDG half 1
        if (act) {
#pragma unroll
            for (int q = 0; q < 4; q++) {
                uint4 h;
                h.x = h2u(__floats2half2_rn(br0[q].x, br0[q].y));
                h.y = h2u(__floats2half2_rn(br0[q].z, br0[q].w));
                h.z = h2u(__floats2half2_rn(br1[q].x, br1[q].y));
                h.w = h2u(__floats2half2_rn(br1[q].z, br1[q].w));
                *(uint4*)(smem + nbB + soB[q]) = h;
            }
#pragma unroll
            for (int q = 4; q < 8; q++) {
                br0[q - 4] = gpB[q][0]; br1[q - 4] = gpB[q][1]; gpB[q] += BK / 4;
            }
        }

        // ---- kk 4..7 (sub-tile 1) ----
#pragma unroll
        for (int kk = 0; kk < 4; kk++) {
            uint32_t a[4][4], b[2][4];
#pragma unroll
            for (int i = 0; i < 4; i++)
                ldsm4(a[i], sA + SUB_B + ((aRaw[i] + kk * 32) ^ aM[i]));
#pragma unroll
            for (int j = 0; j < 2; j++)
                ldsm4(b[j], sB + SUB_B + ((bRaw[j] + kk * 32) ^ bM[j]));
#pragma unroll
            for (int i = 0; i < 4; i++)
#pragma unroll
                for (int jn = 0; jn < 4; jn++)
                    mma16816(acc[i][jn], a[i],
                             b[jn >> 1][jn & 1], b[jn >> 1][(jn & 1) + 2]);
        }

        // STS half 1
        if (act) {
#pragma unroll
            for (int q = 4; q < 8; q++) {
                uint4 h;
                h.x = h2u(__floats2half2_rn(br0[q - 4].x, br0[q - 4].y));
                h.y = h2u(__floats2half2_rn(br0[q - 4].z, br0[q - 4].w));
                h.z = h2u(__floats2half2_rn(br1[q - 4].x, br1[q - 4].y));
                h.w = h2u(__floats2half2_rn(br1[q - 4].z, br1[q - 4].w));
                *(uint4*)(smem + nbB + soB[q]) = h;
            }
        }
        cp_commit();
    }

    // ---- epilogue: stage C (128x128 f32) in smem, then fused write ----
    __syncthreads();
    float* cb = (float*)smem;
#pragma unroll
    for (int i = 0; i < 4; i++) {
#pragma unroll
        for (int jn = 0; jn < 4; jn++) {
            int r = mbase + i * 16 + (lane >> 2);
            int c = nbase + jn * 8 + (lane & 3) * 2;
            cb[(size_t)r * BN + c]           = acc[i][jn][0];
            cb[(size_t)r * BN + c + 1]       = acc[i][jn][1];
            cb[(size_t)(r + 8) * BN + c]     = acc[i][jn][2];
            cb[(size_t)(r + 8) * BN + c + 1] = acc[i][jn][3];
        }
    }
    __syncthreads();

    if (MODE == 0) {
        int r = tid >> 1, ch = (tid & 1) * 32;
        if (m0 + r < cnt) {
            __half2* dst = (__half2*)(g_yh + (size_t)(row0 + m0 + r) * I_DIM + n0I + ch);
            const float* gr = cb + (size_t)r * BN + ch;
            const float* ur = gr + 64;
#pragma unroll
            for (int c4 = 0; c4 < 8; c4++) {
                float4 g = *(const float4*)(gr + c4 * 4);
                float4 u = *(const float4*)(ur + c4 * 4);
                float4 v;
                v.x = g.x / (1.f + __expf(-g.x)) * u.x;
                v.y = g.y / (1.f + __expf(-g.y)) * u.y;
                v.z = g.z / (1.f + __expf(-g.z)) * u.z;
                v.w = g.w / (1.f + __expf(-g.w)) * u.w;
                dst[c4 * 2 + 0] = __floats2half2_rn(v.x, v.y);
                dst[c4 * 2 + 1] = __floats2half2_rn(v.z, v.w);
            }
        }
    } else {
        int r = tid >> 1, ch = (tid & 1) * 64;
        if (m0 + r < cnt) {
            __half2* dst = (__half2*)(g_zh + (size_t)(row0 + m0 + r) * H_DIM + n0 + ch);
            const float* srcr = cb + (size_t)r * BN + ch;
#pragma unroll
            for (int c4 = 0; c4 < 16; c4++) {
                float4 v = *(const float4*)(srcr + c4 * 4);
                dst[c4 * 2 + 0] = __floats2half2_rn(v.x, v.y);
                dst[c4 * 2 + 1] = __floats2half2_rn(v.z, v.w);
            }
        }
    }
}

// ---------------- combine: out[t] = w0*z[loc0] + w1*z[loc1] (z fp16) ----------------
__global__ void combine_kernel(float* __restrict__ out) {
    int idx = blockIdx.x * blockDim.x + threadIdx.x;
    int t = idx >> 9;            // H_DIM/4 = 512
    int c = idx & 511;
    int l0 = g_pairloc[2 * t], l1 = g_pairloc[2 * t + 1];
    float w0 = g_topw[2 * t], w1 = g_topw[2 * t + 1];
    const __half2* z0 = (const __half2*)(g_zh + (size_t)l0 * H_DIM) + c * 2;
    const __half2* z1 = (const __half2*)(g_zh + (size_t)l1 * H_DIM) + c * 2;
    float2 a0 = __half22float2(z0[0]), a1 = __half22float2(z0[1]);
    float2 b0 = __half22float2(z1[0]), b1 = __half22float2(z1[1]);
    float4 o;
    o.x = w0 * a0.x + w1 * b0.x;
    o.y = w0 * a0.y + w1 * b0.y;
    o.z = w0 * a1.x + w1 * b1.x;
    o.w = w0 * a1.y + w1 * b1.y;
    ((float4*)out)[idx] = o;
}

// ---------------- launch ----------------
extern "C" void kernel_launch(void* const* d_in, const int* in_sizes, int n_in,
                              void* d_out, int out_size) {
    const float* x  = (const float*)d_in[0];   // [T, H]
    const float* wg = (const float*)d_in[1];   // [E, H]
    const float* w1 = (const float*)d_in[2];   // [E, I, H]
    const float* w3 = (const float*)d_in[3];   // [E, I, H]
    const float* w2 = (const float*)d_in[4];   // [E, H, I]
    float* out = (float*)d_out;                // [T, H]

    cudaFuncSetAttribute(moe_gemm_kernel<0>,
                         cudaFuncAttributeMaxDynamicSharedMemorySize, SMEM_BYTES);
    cudaFuncSetAttribute(moe_gemm_kernel<1>,
                         cudaFuncAttributeMaxDynamicSharedMemorySize, SMEM_BYTES);

    init_kernel<<<1, 32>>>();
    router_kernel<<<T_TOK / 8, 256>>>(x, wg);
    scan_kernel<<<1, 32>>>();
    scatter_kernel<<<T_TOK / 256, 256>>>();

    dim3 g1(I_DIM / 64, T_TOK / BM, E_NUM);    // 16 x 64 x 8, early-exit on cnt
    moe_gemm_kernel<0><<<g1, 256, SMEM_BYTES>>>(w1, w3);

    dim3 g2(H_DIM / BN, T_TOK / BM, E_NUM);    // 16 x 64 x 8
    moe_gemm_kernel<1><<<g2, 256, SMEM_BYTES>>>(w2, nullptr);

    combine_kernel<<<(T_TOK * H_DIM / 4) / 256, 256>>>(out);
}

// round 11
// speedup vs baseline: 1.1199x; 1.1199x over previous
#include <cuda_runtime.h>
#include <cuda_fp16.h>
#include <cstdint>

static constexpr int T_TOK = 8192;
static constexpr int H_DIM = 2048;
static constexpr int E_NUM = 8;
static constexpr int I_DIM = 1024;
static constexpr int NPAIR = T_TOK * 2;

// ---------------- scratch (static device globals; no allocations) ----------------
__device__ __align__(128) __half g_xh[(size_t)T_TOK * H_DIM];   // x in fp16 (router writes)
__device__ __align__(128) __half g_yh[(size_t)NPAIR * I_DIM];   // silu(g)*u, fp16
__device__ __align__(128) __half g_zh[(size_t)NPAIR * H_DIM];   // down-proj out, fp16
__device__ int   g_topidx[NPAIR];
__device__ float g_topw[NPAIR];
__device__ int   g_pairloc[NPAIR];
__device__ int   g_bucket[NPAIR];
__device__ int   g_counts[E_NUM];
__device__ int   g_offsets[E_NUM + 1];
__device__ int   g_cursors[E_NUM];

// ---------------- PTX helpers ----------------
#define SWZ128(o) ((o) ^ (((o) >> 3) & 0x70))

__device__ __forceinline__ uint32_t h2u(__half2 h) {
    return *reinterpret_cast<uint32_t*>(&h);
}
__device__ __forceinline__ void cp16(uint32_t dst, const void* src) {
    asm volatile("cp.async.cg.shared.global [%0], [%1], 16;" :: "r"(dst), "l"(src) : "memory");
}
__device__ __forceinline__ void cp_commit() {
    asm volatile("cp.async.commit_group;" ::: "memory");
}
template <int N>
__device__ __forceinline__ void cp_wait() {
    asm volatile("cp.async.wait_group %0;" :: "n"(N) : "memory");
}
__device__ __forceinline__ void ldsm4(uint32_t* d, uint32_t addr) {
    asm volatile("ldmatrix.sync.aligned.m8n8.x4.shared.b16 {%0,%1,%2,%3}, [%4];"
                 : "=r"(d[0]), "=r"(d[1]), "=r"(d[2]), "=r"(d[3]) : "r"(addr));
}
__device__ __forceinline__ void mma16816(float* c, const uint32_t* a, uint32_t b0, uint32_t b1) {
    asm volatile(
        "mma.sync.aligned.m16n8k16.row.col.f32.f16.f16.f32 "
        "{%0,%1,%2,%3}, {%4,%5,%6,%7}, {%8,%9}, {%0,%1,%2,%3};"
        : "+f"(c[0]), "+f"(c[1]), "+f"(c[2]), "+f"(c[3])
        : "r"(a[0]), "r"(a[1]), "r"(a[2]), "r"(a[3]), "r"(b0), "r"(b1));
}

// ---------------- tiny setup kernels ----------------
__global__ void init_kernel() {
    int i = threadIdx.x;
    if (i < E_NUM) { g_counts[i] = 0; g_cursors[i] = 0; }
}

// One warp per token: router logits + top-2, AND writes the fp16 copy of x.
__global__ void router_kernel(const float* __restrict__ x,
                              const float* __restrict__ wg) {
    int warp = threadIdx.x >> 5, lane = threadIdx.x & 31;
    int t = blockIdx.x * 8 + warp;
    if (t >= T_TOK) return;
    float acc[E_NUM];
#pragma unroll
    for (int e = 0; e < E_NUM; e++) acc[e] = 0.f;
    const float4* xr = (const float4*)(x + (size_t)t * H_DIM);
    __half2* xh = (__half2*)(g_xh + (size_t)t * H_DIM);
    for (int h4 = lane; h4 < H_DIM / 4; h4 += 32) {
        float4 xv = xr[h4];
        xh[h4 * 2 + 0] = __floats2half2_rn(xv.x, xv.y);
        xh[h4 * 2 + 1] = __floats2half2_rn(xv.z, xv.w);
#pragma unroll
        for (int e = 0; e < E_NUM; e++) {
            float4 wv = ((const float4*)(wg + (size_t)e * H_DIM))[h4];
            acc[e] += xv.x * wv.x + xv.y * wv.y + xv.z * wv.z + xv.w * wv.w;
        }
    }
#pragma unroll
    for (int e = 0; e < E_NUM; e++)
#pragma unroll
        for (int off = 16; off; off >>= 1)
            acc[e] += __shfl_xor_sync(0xffffffffu, acc[e], off);
    if (lane == 0) {
        int i0 = 0;
        for (int e = 1; e < E_NUM; e++) if (acc[e] > acc[i0]) i0 = e;
        int i1 = (i0 == 0) ? 1 : 0;
        for (int e = 0; e < E_NUM; e++) if (e != i0 && acc[e] > acc[i1]) i1 = e;
        float w0 = 1.f / (1.f + expf(acc[i1] - acc[i0]));
        g_topidx[2 * t] = i0; g_topidx[2 * t + 1] = i1;
        g_topw[2 * t] = w0;   g_topw[2 * t + 1] = 1.f - w0;
        atomicAdd(&g_counts[i0], 1);
        atomicAdd(&g_counts[i1], 1);
    }
}

__global__ void scan_kernel() {
    if (threadIdx.x == 0) {
        int s = 0;
        for (int e = 0; e < E_NUM; e++) { g_offsets[e] = s; s += g_counts[e]; }
        g_offsets[E_NUM] = s;
    }
}

__global__ void scatter_kernel() {
    int t = blockIdx.x * blockDim.x + threadIdx.x;
    if (t >= T_TOK) return;
#pragma unroll
    for (int k = 0; k < 2; k++) {
        int e = g_topidx[2 * t + k];
        int pos = atomicAdd(&g_cursors[e], 1);
        int glob = g_offsets[e] + pos;
        g_bucket[glob] = t;
        g_pairloc[2 * t + k] = glob;
    }
}

// ---------------- fp16 mma grouped GEMM: 4 warps x (64x64), 2 CTAs/SM ----------------
// Tile 128x128, BK=64. Stage = A 16KB fp16 + B 16KB fp16 = 32KB; NSTG=3 -> 96KB dyn.
// A (fp16, cp.async): MODE 0 = gather(g_xh); MODE 1 = g_yh contiguous.
// B (fp32 -> fp16 in-register, STS in two half-batches): MODE 0 rows 0-63 = w1,
//   rows 64-127 = w3 (64 I-feats/block); MODE 1 = w2 rows.
static constexpr int BM = 128, BN = 128, BK = 64;      // BK in halves (128B fp16 rows)
static constexpr int NSTG = 3;
static constexpr int MAT_B = 128 * 128;                // 16384 bytes per fp16 tile
static constexpr int STG_B = 2 * MAT_B;                // 32768 per stage
static constexpr int SMEM_BYTES = NSTG * STG_B;        // 98304

template <int MODE>
__global__ __launch_bounds__(128, 2)
void moe_gemm_kernel(const float* __restrict__ W0,    // w1 / w2 (fp32)
                     const float* __restrict__ W1)    // w3 / unused
{
    constexpr int KD = (MODE == 0) ? H_DIM : I_DIM;
    constexpr int NK = KD / BK;                         // 32 / 16

    const int e    = blockIdx.z;
    const int row0 = g_offsets[e];
    const int cnt  = g_offsets[e + 1] - row0;
    const int m0   = blockIdx.y * BM;
    if (m0 >= cnt) return;

    extern __shared__ char smem[];
    const uint32_t smb = (uint32_t)__cvta_generic_to_shared(smem);

    const int tid = threadIdx.x;                        // 0..127
    const int wid = tid >> 5, lane = tid & 31;
    const int wm = wid & 1, wn = wid >> 1;              // 2(M) x 2(N) warps
    const int mbase = wm * 64, nbase = wn * 64;

    const int n0I = blockIdx.x * 64;                    // MODE 0
    const int n0  = blockIdx.x * BN;                    // MODE 1

    const int r8 = tid >> 3;                            // 0..15: row-within-16-group
    const int c8 = tid & 7;                             // 16B/32B column chunk

    // ---- A: 8 cp.async chunks (16B) per thread per stage; chunk q -> row 16q+r8 ----
    const __half* gpA[8];
#pragma unroll
    for (int q = 0; q < 8; q++) {
        int r = q * 16 + r8;
        int lr = m0 + r; if (lr >= cnt) lr = cnt - 1;
        size_t arow = (MODE == 0) ? (size_t)g_bucket[row0 + lr] * KD
                                  : (size_t)(row0 + lr) * KD;
        gpA[q] = ((MODE == 0) ? g_xh : g_yh) + arow + c8 * 8;
    }
    // ---- B: 8 chunks (32B fp32 -> 16B fp16) per thread per stage ----
    // chunk q -> B-row 16q+r8; MODE 0: q<4 -> w1 row, q>=4 -> w3 row (r-64).
    const float4* gpB[8];
#pragma unroll
    for (int q = 0; q < 8; q++) {
        int r = q * 16 + r8;
        const float* bb;
        if (MODE == 0)
            bb = (r < 64) ? (W0 + ((size_t)e * I_DIM + (n0I + r)) * KD)
                          : (W1 + ((size_t)e * I_DIM + (n0I + r - 64)) * KD);
        else
            bb = W0 + ((size_t)e * H_DIM + (n0 + r)) * KD;
        gpB[q] = (const float4*)(bb + c8 * 8);
    }
    // smem byte offsets (recomputed cheaply, swizzled): A chunk q, B chunk q
    uint32_t soA[8], soB[8];
#pragma unroll
    for (int q = 0; q < 8; q++) {
        int r = q * 16 + r8;
        soA[q] = (uint32_t)SWZ128(r * 128 + c8 * 16);
        soB[q] = (uint32_t)MAT_B + (uint32_t)SWZ128(r * 128 + c8 * 16);
    }

    // ---- ldmatrix address bases ----
    const int lrow = lane & 15;
    const uint32_t kc16 = (uint32_t)(lane >> 4) * 16;
    uint32_t aRaw[4], aM[4], bRaw[4], bM[4];
#pragma unroll
    for (int i = 0; i < 4; i++) {
        int r = mbase + i * 16 + lrow;
        aRaw[i] = (uint32_t)r * 128 + kc16;
        aM[i] = (uint32_t)(r & 7) << 4;
    }
#pragma unroll
    for (int j = 0; j < 4; j++) {
        int r = nbase + j * 16 + lrow;
        bRaw[j] = (uint32_t)r * 128 + kc16;
        bM[j] = (uint32_t)(r & 7) << 4;
    }

    float acc[4][8][4];                                 // 4 m16 x 8 n8 x 4
#pragma unroll
    for (int i = 0; i < 4; i++)
#pragma unroll
        for (int j = 0; j < 8; j++)
#pragma unroll
            for (int q = 0; q < 4; q++) acc[i][j][q] = 0.f;

    // ---- prologue: fill slots 0..NSTG-2 (A async; B blocking LDG+cvt+STS) ----
#pragma unroll
    for (int s = 0; s < NSTG - 1; s++) {
        uint32_t base = smb + (uint32_t)s * STG_B;
#pragma unroll
        for (int q = 0; q < 8; q++) { cp16(base + soA[q], gpA[q]); gpA[q] += BK; }
#pragma unroll
        for (int q = 0; q < 8; q++) {
            float4 v0 = gpB[q][0], v1 = gpB[q][1];
            gpB[q] += BK / 4;
            uint4 h;
            h.x = h2u(__floats2half2_rn(v0.x, v0.y));
            h.y = h2u(__floats2half2_rn(v0.z, v0.w));
            h.z = h2u(__floats2half2_rn(v1.x, v1.y));
            h.w = h2u(__floats2half2_rn(v1.z, v1.w));
            *(uint4*)(smem + (size_t)s * STG_B + soB[q]) = h;
        }
        cp_commit();
    }

    // ---- mainloop ----
    for (int it = 0; it < NK; it++) {
        cp_wait<NSTG - 2>();
        __syncthreads();

        const bool act = (it + NSTG - 1 < NK);
        const uint32_t slot = (uint32_t)((it + NSTG - 1) % NSTG);
        const uint32_t nb = slot * STG_B;

        // issue A prefetch + B batch0 loads immediately (latency hidden by MMAs)
        float4 br0[4], br1[4];
        if (act) {
            uint32_t base = smb + nb;
#pragma unroll
            for (int q = 0; q < 8; q++) { cp16(base + soA[q], gpA[q]); gpA[q] += BK; }
#pragma unroll
            for (int q = 0; q < 4; q++) {
                br0[q] = gpB[q][0]; br1[q] = gpB[q][1]; gpB[q] += BK / 4;
            }
        }

        const uint32_t sA = smb + (uint32_t)(it % NSTG) * STG_B;
        const uint32_t sB = sA + MAT_B;

        // ---- kk 0..1 ----
#pragma unroll
        for (int kk = 0; kk < 2; kk++) {
            uint32_t a[4][4], b[2][4];
#pragma unroll
            for (int i = 0; i < 4; i++)
                ldsm4(a[i], sA + ((aRaw[i] + kk * 32) ^ aM[i]));
#pragma unroll
            for (int jh = 0; jh < 2; jh++) {
#pragma unroll
                for (int jf = 0; jf < 2; jf++)
                    ldsm4(b[jf], sB + ((bRaw[jh * 2 + jf] + kk * 32) ^ bM[jh * 2 + jf]));
#pragma unroll
                for (int i = 0; i < 4; i++)
#pragma unroll
                    for (int jn = 0; jn < 4; jn++)
                        mma16816(acc[i][jh * 4 + jn], a[i],
                                 b[jn >> 1][jn & 1], b[jn >> 1][(jn & 1) + 2]);
            }
        }

        // STS batch0; LDG batch1
        if (act) {
#pragma unroll
            for (int q = 0; q < 4; q++) {
                uint4 h;
                h.x = h2u(__floats2half2_rn(br0[q].x, br0[q].y));
                h.y = h2u(__floats2half2_rn(br0[q].z, br0[q].w));
                h.z = h2u(__floats2half2_rn(br1[q].x, br1[q].y));
                h.w = h2u(__floats2half2_rn(br1[q].z, br1[q].w));
                *(uint4*)(smem + nb + soB[q]) = h;
            }
#pragma unroll
            for (int q = 4; q < 8; q++) {
                br0[q - 4] = gpB[q][0]; br1[q - 4] = gpB[q][1]; gpB[q] += BK / 4;
            }
        }

        // ---- kk 2..3 ----
#pragma unroll
        for (int kk = 2; kk < 4; kk++) {
            uint32_t a[4][4], b[2][4];
#pragma unroll
            for (int i = 0; i < 4; i++)
                ldsm4(a[i], sA + ((aRaw[i] + kk * 32) ^ aM[i]));
#pragma unroll
            for (int jh = 0; jh < 2; jh++) {
#pragma unroll
                for (int jf = 0; jf < 2; jf++)
                    ldsm4(b[jf], sB + ((bRaw[jh * 2 + jf] + kk * 32) ^ bM[jh * 2 + jf]));
#pragma unroll
                for (int i = 0; i < 4; i++)
#pragma unroll
                    for (int jn = 0; jn < 4; jn++)
                        mma16816(acc[i][jh * 4 + jn], a[i],
                                 b[jn >> 1][jn & 1], b[jn >> 1][(jn & 1) + 2]);
            }
        }

        // STS batch1
        if (act) {
#pragma unroll
            for (int q = 4; q < 8; q++) {
                uint4 h;
                h.x = h2u(__floats2half2_rn(br0[q - 4].x, br0[q - 4].y));
                h.y = h2u(__floats2half2_rn(br0[q - 4].z, br0[q - 4].w));
                h.z = h2u(__floats2half2_rn(br1[q - 4].x, br1[q - 4].y));
                h.w = h2u(__floats2half2_rn(br1[q - 4].z, br1[q - 4].w));
                *(uint4*)(smem + nb + soB[q]) = h;
            }
        }
        cp_commit();
    }

    // ---- epilogue: stage C (128x128 f32, 64KB) in smem, then fused write ----
    __syncthreads();
    float* cb = (float*)smem;
#pragma unroll
    for (int i = 0; i < 4; i++) {
#pragma unroll
        for (int jn = 0; jn < 8; jn++) {
            int r = mbase + i * 16 + (lane >> 2);
            int c = nbase + jn * 8 + (lane & 3) * 2;
            cb[(size_t)r * BN + c]           = acc[i][jn][0];
            cb[(size_t)r * BN + c + 1]       = acc[i][jn][1];
            cb[(size_t)(r + 8) * BN + c]     = acc[i][jn][2];
            cb[(size_t)(r + 8) * BN + c + 1] = acc[i][jn][3];
        }
    }
    __syncthreads();

    if (MODE == 0) {
        int r = tid;                                     // one row per thread
        if (m0 + r < cnt) {
            __half2* dst = (__half2*)(g_yh + (size_t)(row0 + m0 + r) * I_DIM + n0I);
            const float* gr = cb + (size_t)r * BN;
            const float* ur = gr + 64;
#pragma unroll
            for (int c4 = 0; c4 < 16; c4++) {
                float4 g = *(const float4*)(gr + c4 * 4);
                float4 u = *(const float4*)(ur + c4 * 4);
                float4 v;
                v.x = g.x / (1.f + __expf(-g.x)) * u.x;
                v.y = g.y / (1.f + __expf(-g.y)) * u.y;
                v.z = g.z / (1.f + __expf(-g.z)) * u.z;
                v.w = g.w / (1.f + __expf(-g.w)) * u.w;
                dst[c4 * 2 + 0] = __floats2half2_rn(v.x, v.y);
                dst[c4 * 2 + 1] = __floats2half2_rn(v.z, v.w);
            }
        }
    } else {
        int r = tid;
        if (m0 + r < cnt) {
            __half2* dst = (__half2*)(g_zh + (size_t)(row0 + m0 + r) * H_DIM + n0);
            const float* srcr = cb + (size_t)r * BN;
#pragma unroll
            for (int c4 = 0; c4 < 32; c4++) {
                float4 v = *(const float4*)(srcr + c4 * 4);
                dst[c4 * 2 + 0] = __floats2half2_rn(v.x, v.y);
                dst[c4 * 2 + 1] = __floats2half2_rn(v.z, v.w);
            }
        }
    }
}

// ---------------- combine: out[t] = w0*z[loc0] + w1*z[loc1] (z fp16) ----------------
__global__ void combine_kernel(float* __restrict__ out) {
    int idx = blockIdx.x * blockDim.x + threadIdx.x;
    int t = idx >> 9;            // H_DIM/4 = 512
    int c = idx & 511;
    int l0 = g_pairloc[2 * t], l1 = g_pairloc[2 * t + 1];
    float w0 = g_topw[2 * t], w1 = g_topw[2 * t + 1];
    const __half2* z0 = (const __half2*)(g_zh + (size_t)l0 * H_DIM) + c * 2;
    const __half2* z1 = (const __half2*)(g_zh + (size_t)l1 * H_DIM) + c * 2;
    float2 a0 = __half22float2(z0[0]), a1 = __half22float2(z0[1]);
    float2 b0 = __half22float2(z1[0]), b1 = __half22float2(z1[1]);
    float4 o;
    o.x = w0 * a0.x + w1 * b0.x;
    o.y = w0 * a0.y + w1 * b0.y;
    o.z = w0 * a1.x + w1 * b1.x;
    o.w = w0 * a1.y + w1 * b1.y;
    ((float4*)out)[idx] = o;
}

// ---------------- launch ----------------
extern "C" void kernel_launch(void* const* d_in, const int* in_sizes, int n_in,
                              void* d_out, int out_size) {
    const float* x  = (const float*)d_in[0];   // [T, H]
    const float* wg = (const float*)d_in[1];   // [E, H]
    const float* w1 = (const float*)d_in[2];   // [E, I, H]
    const float* w3 = (const float*)d_in[3];   // [E, I, H]
    const float* w2 = (const float*)d_in[4];   // [E, H, I]
    float* out = (float*)d_out;                // [T, H]

    cudaFuncSetAttribute(moe_gemm_kernel<0>,
                         cudaFuncAttributeMaxDynamicSharedMemorySize, SMEM_BYTES);
    cudaFuncSetAttribute(moe_gemm_kernel<1>,
                         cudaFuncAttributeMaxDynamicSharedMemorySize, SMEM_BYTES);

    init_kernel<<<1, 32>>>();
    router_kernel<<<T_TOK / 8, 256>>>(x, wg);
    scan_kernel<<<1, 32>>>();
    scatter_kernel<<<T_TOK / 256, 256>>>();

    dim3 g1(I_DIM / 64, T_TOK / BM, E_NUM);    // 16 x 64 x 8, early-exit on cnt
    moe_gemm_kernel<0><<<g1, 128, SMEM_BYTES>>>(w1, w3);

    dim3 g2(H_DIM / BN, T_TOK / BM, E_NUM);    // 16 x 64 x 8
    moe_gemm_kernel<1><<<g2, 128, SMEM_BYTES>>>(w2, nullptr);

    combine_kernel<<<(T_TOK * H_DIM / 4) / 256, 256>>>(out);
}

// round 15
// speedup vs baseline: 1.1203x; 1.0003x over previous
#include <cuda_runtime.h>
#include <cuda_fp16.h>
#include <cstdint>

static constexpr int T_TOK = 8192;
static constexpr int H_DIM = 2048;
static constexpr int E_NUM = 8;
static constexpr int I_DIM = 1024;
static constexpr int NPAIR = T_TOK * 2;

// ---------------- scratch (static device globals; no allocations) ----------------
__device__ __align__(128) __half g_xh[(size_t)T_TOK * H_DIM];   // x in fp16 (router writes)
__device__ __align__(128) __half g_yh[(size_t)NPAIR * I_DIM];   // silu(g)*u, fp16
__device__ int   g_topidx[NPAIR];
__device__ float g_topw[NPAIR];
__device__ float g_wbuf[NPAIR];                                 // bucket row -> combine weight
__device__ int   g_bucket[NPAIR];                               // bucket row -> token id
__device__ int   g_counts[E_NUM];
__device__ int   g_offsets[E_NUM + 1];
__device__ int   g_cursors[E_NUM];

// ---------------- PTX helpers ----------------
#define SWZ128(o) ((o) ^ (((o) >> 3) & 0x70))

__device__ __forceinline__ uint32_t h2u(__half2 h) {
    return *reinterpret_cast<uint32_t*>(&h);
}
__device__ __forceinline__ void cp16(uint32_t dst, const void* src) {
    asm volatile("cp.async.cg.shared.global [%0], [%1], 16;" :: "r"(dst), "l"(src) : "memory");
}
__device__ __forceinline__ void cp_commit() {
    asm volatile("cp.async.commit_group;" ::: "memory");
}
template <int N>
__device__ __forceinline__ void cp_wait() {
    asm volatile("cp.async.wait_group %0;" :: "n"(N) : "memory");
}
__device__ __forceinline__ void ldsm4(uint32_t* d, uint32_t addr) {
    asm volatile("ldmatrix.sync.aligned.m8n8.x4.shared.b16 {%0,%1,%2,%3}, [%4];"
                 : "=r"(d[0]), "=r"(d[1]), "=r"(d[2]), "=r"(d[3]) : "r"(addr));
}
__device__ __forceinline__ void mma16816(float* c, const uint32_t* a, uint32_t b0, uint32_t b1) {
    asm volatile(
        "mma.sync.aligned.m16n8k16.row.col.f32.f16.f16.f32 "
        "{%0,%1,%2,%3}, {%4,%5,%6,%7}, {%8,%9}, {%0,%1,%2,%3};"
        : "+f"(c[0]), "+f"(c[1]), "+f"(c[2]), "+f"(c[3])
        : "r"(a[0]), "r"(a[1]), "r"(a[2]), "r"(a[3]), "r"(b0), "r"(b1));
}

// ---------------- tiny setup kernels ----------------
__global__ void init_kernel() {
    int i = threadIdx.x;
    if (i < E_NUM) { g_counts[i] = 0; g_cursors[i] = 0; }
}

__global__ void zero_out_kernel(float* __restrict__ out) {
    int i = blockIdx.x * blockDim.x + threadIdx.x;          // T*H/4 threads
    ((float4*)out)[i] = make_float4(0.f, 0.f, 0.f, 0.f);
}

// One warp per token: router logits + top-2, AND writes the fp16 copy of x.
__global__ void router_kernel(const float* __restrict__ x,
                              const float* __restrict__ wg) {
    int warp = threadIdx.x >> 5, lane = threadIdx.x & 31;
    int t = blockIdx.x * 8 + warp;
    if (t >= T_TOK) return;
    float acc[E_NUM];
#pragma unroll
    for (int e = 0; e < E_NUM; e++) acc[e] = 0.f;
    const float4* xr = (const float4*)(x + (size_t)t * H_DIM);
    __half2* xh = (__half2*)(g_xh + (size_t)t * H_DIM);
    for (int h4 = lane; h4 < H_DIM / 4; h4 += 32) {
        float4 xv = xr[h4];
        xh[h4 * 2 + 0] = __floats2half2_rn(xv.x, xv.y);
        xh[h4 * 2 + 1] = __floats2half2_rn(xv.z, xv.w);
#pragma unroll
        for (int e = 0; e < E_NUM; e++) {
            float4 wv = ((const float4*)(wg + (size_t)e * H_DIM))[h4];
            acc[e] += xv.x * wv.x + xv.y * wv.y + xv.z * wv.z + xv.w * wv.w;
        }
    }
#pragma unroll
    for (int e = 0; e < E_NUM; e++)
#pragma unroll
        for (int off = 16; off; off >>= 1)
            acc[e] += __shfl_xor_sync(0xffffffffu, acc[e], off);
    if (lane == 0) {
        int i0 = 0;
        for (int e = 1; e < E_NUM; e++) if (acc[e] > acc[i0]) i0 = e;
        int i1 = (i0 == 0) ? 1 : 0;
        for (int e = 0; e < E_NUM; e++) if (e != i0 && acc[e] > acc[i1]) i1 = e;
        float w0 = 1.f / (1.f + expf(acc[i1] - acc[i0]));
        g_topidx[2 * t] = i0; g_topidx[2 * t + 1] = i1;
        g_topw[2 * t] = w0;   g_topw[2 * t + 1] = 1.f - w0;
        atomicAdd(&g_counts[i0], 1);
        atomicAdd(&g_counts[i1], 1);
    }
}

__global__ void scan_kernel() {
    if (threadIdx.x == 0) {
        int s = 0;
        for (int e = 0; e < E_NUM; e++) { g_offsets[e] = s; s += g_counts[e]; }
        g_offsets[E_NUM] = s;
    }
}

__global__ void scatter_kernel() {
    int t = blockIdx.x * blockDim.x + threadIdx.x;
    if (t >= T_TOK) return;
#pragma unroll
    for (int k = 0; k < 2; k++) {
        int e = g_topidx[2 * t + k];
        int pos = atomicAdd(&g_cursors[e], 1);
        int glob = g_offsets[e] + pos;
        g_bucket[glob] = t;
        g_wbuf[glob] = g_topw[2 * t + k];
    }
}

// ---------------- fp16 mma grouped GEMM: 4 warps x (64x64), 2 CTAs/SM ----------------
// Tile 128x128, BK=64. Stage = A 16KB fp16 + B 16KB fp16 = 32KB; NSTG=3 -> 96KB dyn.
// A (fp16, cp.async): MODE 0 = gather(g_xh); MODE 1 = g_yh contiguous.
// B (fp32 -> fp16 in-register, STS in two half-batches): MODE 0 rows 0-63 = w1,
//   rows 64-127 = w3 (64 I-feats/block); MODE 1 = w2 rows.
// MODE 0 epilogue: y = silu(g)*u -> g_yh fp16.
// MODE 1 epilogue: out[token] += w * acc  (fp32 atomicAdd; exactly 2 adds/element
//   onto a zeroed buffer -> bitwise deterministic by commutativity).
static constexpr int BM = 128, BN = 128, BK = 64;      // BK in halves (128B fp16 rows)
static constexpr int NSTG = 3;
static constexpr int MAT_B = 128 * 128;                // 16384 bytes per fp16 tile
static constexpr int STG_B = 2 * MAT_B;                // 32768 per stage
static constexpr int SMEM_BYTES = NSTG * STG_B;        // 98304

template <int MODE>
__global__ __launch_bounds__(128, 2)
void moe_gemm_kernel(const float* __restrict__ W0,    // w1 / w2 (fp32)
                     const float* __restrict__ W1,    // w3 / unused
                     float* __restrict__ out)         // unused / output
{
    constexpr int KD = (MODE == 0) ? H_DIM : I_DIM;
    constexpr int NK = KD / BK;                         // 32 / 16

    const int e    = blockIdx.z;
    const int row0 = g_offsets[e];
    const int cnt  = g_offsets[e + 1] - row0;
    const int m0   = blockIdx.y * BM;
    if (m0 >= cnt) return;

    extern __shared__ char smem[];
    const uint32_t smb = (uint32_t)__cvta_generic_to_shared(smem);

    const int tid = threadIdx.x;                        // 0..127
    const int wid = tid >> 5, lane = tid & 31;
    const int wm = wid & 1, wn = wid >> 1;              // 2(M) x 2(N) warps
    const int mbase = wm * 64, nbase = wn * 64;

    const int n0I = blockIdx.x * 64;                    // MODE 0
    const int n0  = blockIdx.x * BN;                    // MODE 1

    const int r8 = tid >> 3;                            // 0..15
    const int c8 = tid & 7;

    // ---- A: 8 cp.async chunks (16B) per thread per stage; chunk q -> row 16q+r8 ----
    const __half* gpA[8];
#pragma unroll
    for (int q = 0; q < 8; q++) {
        int r = q * 16 + r8;
        int lr = m0 + r; if (lr >= cnt) lr = cnt - 1;
        size_t arow = (MODE == 0) ? (size_t)g_bucket[row0 + lr] * KD
                                  : (size_t)(row0 + lr) * KD;
        gpA[q] = ((MODE == 0) ? g_xh : g_yh) + arow + c8 * 8;
    }
    // ---- B: 8 chunks (32B fp32 -> 16B fp16) per thread per stage ----
    const float4* gpB[8];
#pragma unroll
    for (int q = 0; q < 8; q++) {
        int r = q * 16 + r8;
        const float* bb;
        if (MODE == 0)
            bb = (r < 64) ? (W0 + ((size_t)e * I_DIM + (n0I + r)) * KD)
                          : (W1 + ((size_t)e * I_DIM + (n0I + r - 64)) * KD);
        else
            bb = W0 + ((size_t)e * H_DIM + (n0 + r)) * KD;
        gpB[q] = (const float4*)(bb + c8 * 8);
    }
    uint32_t soA[8], soB[8];
#pragma unroll
    for (int q = 0; q < 8; q++) {
        int r = q * 16 + r8;
        soA[q] = (uint32_t)SWZ128(r * 128 + c8 * 16);
        soB[q] = (uint32_t)MAT_B + (uint32_t)SWZ128(r * 128 + c8 * 16);
    }

    // ---- ldmatrix address bases ----
    const int lrow = lane & 15;
    const uint32_t kc16 = (uint32_t)(lane >> 4) * 16;
    uint32_t aRaw[4], aM[4], bRaw[4], bM[4];
#pragma unroll
    for (int i = 0; i < 4; i++) {
        int r = mbase + i * 16 + lrow;
        aRaw[i] = (uint32_t)r * 128 + kc16;
        aM[i] = (uint32_t)(r & 7) << 4;
    }
#pragma unroll
    for (int j = 0; j < 4; j++) {
        int r = nbase + j * 16 + lrow;
        bRaw[j] = (uint32_t)r * 128 + kc16;
        bM[j] = (uint32_t)(r & 7) << 4;
    }

    float acc[4][8][4];
#pragma unroll
    for (int i = 0; i < 4; i++)
#pragma unroll
        for (int j = 0; j < 8; j++)
#pragma unroll
            for (int q = 0; q < 4; q++) acc[i][j][q] = 0.f;

    // ---- prologue ----
#pragma unroll
    for (int s = 0; s < NSTG - 1; s++) {
        uint32_t base = smb + (uint32_t)s * STG_B;
#pragma unroll
        for (int q = 0; q < 8; q++) { cp16(base + soA[q], gpA[q]); gpA[q] += BK; }
#pragma unroll
        for (int q = 0; q < 8; q++) {
            float4 v0 = gpB[q][0], v1 = gpB[q][1];
            gpB[q] += BK / 4;
            uint4 h;
            h.x = h2u(__floats2half2_rn(v0.x, v0.y));
            h.y = h2u(__floats2half2_rn(v0.z, v0.w));
            h.z = h2u(__floats2half2_rn(v1.x, v1.y));
            h.w = h2u(__floats2half2_rn(v1.z, v1.w));
            *(uint4*)(smem + (size_t)s * STG_B + soB[q]) = h;
        }
        cp_commit();
    }

    // ---- mainloop ----
    for (int it = 0; it < NK; it++) {
        cp_wait<NSTG - 2>();
        __syncthreads();

        const bool act = (it + NSTG - 1 < NK);
        const uint32_t slot = (uint32_t)((it + NSTG - 1) % NSTG);
        const uint32_t nb = slot * STG_B;

        float4 br0[4], br1[4];
        if (act) {
            uint32_t base = smb + nb;
#pragma unroll
            for (int q = 0; q < 8; q++) { cp16(base + soA[q], gpA[q]); gpA[q] += BK; }
#pragma unroll
            for (int q = 0; q < 4; q++) {
                br0[q] = gpB[q][0]; br1[q] = gpB[q][1]; gpB[q] += BK / 4;
            }
        }

        const uint32_t sA = smb + (uint32_t)(it % NSTG) * STG_B;
        const uint32_t sB = sA + MAT_B;

        // ---- kk 0..1 ----
#pragma unroll
        for (int kk = 0; kk < 2; kk++) {
            uint32_t a[4][4], b[2][4];
#pragma unroll
            for (int i = 0; i < 4; i++)
                ldsm4(a[i], sA + ((aRaw[i] + kk * 32) ^ aM[i]));
#pragma unroll
            for (int jh = 0; jh < 2; jh++) {
#pragma unroll
                for (int jf = 0; jf < 2; jf++)
                    ldsm4(b[jf], sB + ((bRaw[jh * 2 + jf] + kk * 32) ^ bM[jh * 2 + jf]));
#pragma unroll
                for (int i = 0; i < 4; i++)
#pragma unroll
                    for (int jn = 0; jn < 4; jn++)
                        mma16816(acc[i][jh * 4 + jn], a[i],
                                 b[jn >> 1][jn & 1], b[jn >> 1][(jn & 1) + 2]);
            }
        }

        // STS batch0; LDG batch1
        if (act) {
#pragma unroll
            for (int q = 0; q < 4; q++) {
                uint4 h;
                h.x = h2u(__floats2half2_rn(br0[q].x, br0[q].y));
                h.y = h2u(__floats2half2_rn(br0[q].z, br0[q].w));
                h.z = h2u(__floats2half2_rn(br1[q].x, br1[q].y));
                h.w = h2u(__floats2half2_rn(br1[q].z, br1[q].w));
                *(uint4*)(smem + nb + soB[q]) = h;
            }
#pragma unroll
            for (int q = 4; q < 8; q++) {
                br0[q - 4] = gpB[q][0]; br1[q - 4] = gpB[q][1]; gpB[q] += BK / 4;
            }
        }

        // ---- kk 2..3 ----
#pragma unroll
        for (int kk = 2; kk < 4; kk++) {
            uint32_t a[4][4], b[2][4];
#pragma unroll
            for (int i = 0; i < 4; i++)
                ldsm4(a[i], sA + ((aRaw[i] + kk * 32) ^ aM[i]));
#pragma unroll
            for (int jh = 0; jh < 2; jh++) {
#pragma unroll
                for (int jf = 0; jf < 2; jf++)
                    ldsm4(b[jf], sB + ((bRaw[jh * 2 + jf] + kk * 32) ^ bM[jh * 2 + jf]));
#pragma unroll
                for (int i = 0; i < 4; i++)
#pragma unroll
                    for (int jn = 0; jn < 4; jn++)
                        mma16816(acc[i][jh * 4 + jn], a[i],
                                 b[jn >> 1][jn & 1], b[jn >> 1][(jn & 1) + 2]);
            }
        }

        // STS batch1
        if (act) {
#pragma unroll
            for (int q = 4; q < 8; q++) {
                uint4 h;
                h.x = h2u(__floats2half2_rn(br0[q - 4].x, br0[q - 4].y));
                h.y = h2u(__floats2half2_rn(br0[q - 4].z, br0[q - 4].w));
                h.z = h2u(__floats2half2_rn(br1[q - 4].x, br1[q - 4].y));
                h.w = h2u(__floats2half2_rn(br1[q - 4].z, br1[q - 4].w));
                *(uint4*)(smem + nb + soB[q]) = h;
            }
        }
        cp_commit();
    }

    // ---- epilogue: stage C (128x128 f32, 64KB) in smem ----
    __syncthreads();
    float* cb = (float*)smem;
#pragma unroll
    for (int i = 0; i < 4; i++) {
#pragma unroll
        for (int jn = 0; jn < 8; jn++) {
            int r = mbase + i * 16 + (lane >> 2);
            int c = nbase + jn * 8 + (lane & 3) * 2;
            cb[(size_t)r * BN + c]           = acc[i][jn][0];
            cb[(size_t)r * BN + c + 1]       = acc[i][jn][1];
            cb[(size_t)(r + 8) * BN + c]     = acc[i][jn][2];
            cb[(size_t)(r + 8) * BN + c + 1] = acc[i][jn][3];
        }
    }
    __syncthreads();

    if (MODE == 0) {
        int r = tid;                                     // one row per thread
        if (m0 + r < cnt) {
            __half2* dst = (__half2*)(g_yh + (size_t)(row0 + m0 + r) * I_DIM + n0I);
            const float* gr = cb + (size_t)r * BN;
            const float* ur = gr + 64;
#pragma unroll
            for (int c4 = 0; c4 < 16; c4++) {
                float4 g = *(const float4*)(gr + c4 * 4);
                float4 u = *(const float4*)(ur + c4 * 4);
                float4 v;
                v.x = g.x / (1.f + __expf(-g.x)) * u.x;
                v.y = g.y / (1.f + __expf(-g.y)) * u.y;
                v.z = g.z / (1.f + __expf(-g.z)) * u.z;
                v.w = g.w / (1.f + __expf(-g.w)) * u.w;
                dst[c4 * 2 + 0] = __floats2half2_rn(v.x, v.y);
                dst[c4 * 2 + 1] = __floats2half2_rn(v.z, v.w);
            }
        }
    } else {
        // out[token] += w * acc. Warp handles one row at a time (lanes cover
        // 128 cols as 32 x float4) -> coalesced RED.F32 within each warp step.
        for (int r = wid; r < BM; r += 4) {
            if (m0 + r >= cnt) break;                    // rows beyond cnt: none valid after
            int gl = row0 + m0 + r;
            int tok = g_bucket[gl];
            float w = g_wbuf[gl];
            float* dst = out + (size_t)tok * H_DIM + n0 + lane * 4;
            const float* src = cb + (size_t)r * BN + lane * 4;
            float4 v = *(const float4*)src;
            atomicAdd(dst + 0, w * v.x);
            atomicAdd(dst + 1, w * v.y);
            atomicAdd(dst + 2, w * v.z);
            atomicAdd(dst + 3, w * v.w);
        }
    }
}

// ---------------- launch ----------------
extern "C" void kernel_launch(void* const* d_in, const int* in_sizes, int n_in,
                              void* d_out, int out_size) {
    const float* x  = (const float*)d_in[0];   // [T, H]
    const float* wg = (const float*)d_in[1];   // [E, H]
    const float* w1 = (const float*)d_in[2];   // [E, I, H]
    const float* w3 = (const float*)d_in[3];   // [E, I, H]
    const float* w2 = (const float*)d_in[4];   // [E, H, I]
    float* out = (float*)d_out;                // [T, H]

    cudaFuncSetAttribute(moe_gemm_kernel<0>,
                         cudaFuncAttributeMaxDynamicSharedMemorySize, SMEM_BYTES);
    cudaFuncSetAttribute(moe_gemm_kernel<1>,
                         cudaFuncAttributeMaxDynamicSharedMemorySize, SMEM_BYTES);

    init_kernel<<<1, 32>>>();
    router_kernel<<<T_TOK / 8, 256>>>(x, wg);
    scan_kernel<<<1, 32>>>();
    scatter_kernel<<<T_TOK / 256, 256>>>();
    zero_out_kernel<<<(T_TOK * H_DIM / 4) / 256, 256>>>(out);

    dim3 g1(I_DIM / 64, T_TOK / BM, E_NUM);    // 16 x 64 x 8, early-exit on cnt
    moe_gemm_kernel<0><<<g1, 128, SMEM_BYTES>>>(w1, w3, nullptr);

    dim3 g2(H_DIM / BN, T_TOK / BM, E_NUM);    // 16 x 64 x 8
    moe_gemm_kernel<1><<<g2, 128, SMEM_BYTES>>>(w2, nullptr, out);
}